// round 2
// baseline (speedup 1.0000x reference)
#include <cuda_runtime.h>

typedef unsigned long long ull;

#define UPn 8
#define Bn 32
#define An 64
#define Ln 1632
#define Kc 12
#define NOFF 21
#define NC 48
#define REDn 408

// ---------------- device scratch (static, no runtime alloc) ----------------
__device__ float2 g_tw[UPn][NOFF][Ln];     // exp(+2*pi*i*n*t/L) per (u, window point)
__device__ int    g_m[UPn][Bn];
__device__ float  g_noise[UPn][Bn];
__device__ float2 g_phas[UPn][Bn][Ln];     // exp(+i * 2pi/L * ((m*n) mod L))
__device__ float  g_W[UPn][Bn][144];       // Wiener 12x12, real

// ---------------- f32x2 helpers (sm_100+) ----------------
__device__ __forceinline__ ull ffma2(ull a, ull b, ull c) {
    ull d; asm("fma.rn.f32x2 %0, %1, %2, %3;" : "=l"(d) : "l"(a), "l"(b), "l"(c)); return d;
}
__device__ __forceinline__ ull fmul2(ull a, ull b) {
    ull d; asm("mul.rn.f32x2 %0, %1, %2;" : "=l"(d) : "l"(a), "l"(b)); return d;
}
__device__ __forceinline__ ull pack2(float lo, float hi) {
    ull d; asm("mov.b64 %0, {%1, %2};" : "=l"(d) : "f"(lo), "f"(hi)); return d;
}
__device__ __forceinline__ float2 unpack2(ull v) {
    float lo, hi; asm("mov.b64 {%0, %1}, %2;" : "=f"(lo), "=f"(hi) : "l"(v));
    return make_float2(lo, hi);
}

// ---------------- K0: twiddle tables for the 21-point window DFT ----------------
__global__ void k0_tw(const int* __restrict__ shifts) {
    const int u = blockIdx.x / NOFF, j = blockIdx.x % NOFF;
    const int ideal = ((Kc - shifts[u]) % Kc) * (Ln / Kc);
    int t = ideal + j - 10; t %= Ln; if (t < 0) t += Ln;
    for (int n = threadIdx.x; n < Ln; n += blockDim.x) {
        int r = (n * t) % Ln;                       // <= 1631*1631, fits int32
        double ang = 6.283185307179586476925287 * (double)r / (double)Ln;
        double sn, cs; sincos(ang, &sn, &cs);
        g_tw[u][j][n] = make_float2((float)cs, (float)sn);
    }
}

// ---------------- K1: window DFT + power argmax + noise power, one block per (u,b) ----
__global__ __launch_bounds__(576, 1) void k1_dft(const float* __restrict__ xr_all,
                                                 const float* __restrict__ xi_all,
                                                 const int* __restrict__ shifts) {
    const int u = blockIdx.x / Bn, b = blockIdx.x % Bn;
    __shared__ float2 sx[An][NC + 3];     // +1 extra col for diffs, odd 8B stride (51)
    __shared__ float2 stw[NOFF][NC];
    __shared__ float2 sacc[An][NOFF];
    __shared__ float  spwr[NOFF];
    __shared__ float  snoise;

    const int tid = threadIdx.x;
    const int a2  = tid & 31;             // lane -> antenna (and antenna+32)
    const int wid = tid >> 5;             // 0..17
    const int og  = wid % 3;              // offset group (7 offsets each)
    const int rr  = wid / 3;              // n-residue 0..5

    for (int i = tid; i < An * NOFF; i += 576) ((float2*)sacc)[i] = make_float2(0.f, 0.f);
    if (tid < NOFF) spwr[tid] = 0.f;
    if (tid == 0) snoise = 0.f;

    const float* xr0 = xr_all + (size_t)(u * Bn + b) * An * Ln;
    const float* xi0 = xi_all + (size_t)(u * Bn + b) * An * Ln;

    ull accA[2][7], accB[2][7];
    #pragma unroll
    for (int e = 0; e < 2; e++)
        #pragma unroll
        for (int t = 0; t < 7; t++) { accA[e][t] = 0ull; accB[e][t] = 0ull; }
    float np = 0.f;

    for (int c0 = 0; c0 < Ln; c0 += NC) {
        __syncthreads();
        for (int i = tid; i < An * NC; i += 576) {
            int a = i / NC, n = i - a * NC;
            sx[a][n] = make_float2(xr0[(size_t)a * Ln + c0 + n],
                                   xi0[(size_t)a * Ln + c0 + n]);
        }
        if (c0 + NC < Ln && tid < An)
            sx[tid][NC] = make_float2(xr0[(size_t)tid * Ln + c0 + NC],
                                      xi0[(size_t)tid * Ln + c0 + NC]);
        for (int i = tid; i < NOFF * NC; i += 576) {
            int o = i / NC, n = i - o * NC;
            stw[o][n] = g_tw[u][o][c0 + n];
        }
        __syncthreads();

        for (int n = rr; n < NC; n += 6) {
            ull tw[7];
            #pragma unroll
            for (int t = 0; t < 7; t++) tw[t] = *(const ull*)&stw[og * 7 + t][n];
            #pragma unroll
            for (int e = 0; e < 2; e++) {
                const int a = a2 + e * 32;
                const float2 x = sx[a][n];
                const ull xrp = pack2(x.x, x.x);
                const ull xip = pack2(x.y, x.y);
                #pragma unroll
                for (int t = 0; t < 7; t++) {
                    accA[e][t] = ffma2(xrp, tw[t], accA[e][t]);
                    accB[e][t] = ffma2(xip, tw[t], accB[e][t]);
                }
                if (og == 0 && c0 + n < Ln - 1) {   // each left index covered once
                    float2 x1 = sx[a][n + 1];
                    float dr = x1.x - x.x, di = x1.y - x.y;
                    np += dr * dr + di * di;
                }
            }
        }
    }
    __syncthreads();

    // combine packed accumulators -> complex, reduce over n-residues via smem atomics
    #pragma unroll
    for (int e = 0; e < 2; e++)
        #pragma unroll
        for (int t = 0; t < 7; t++) {
            float2 A = unpack2(accA[e][t]), Bv = unpack2(accB[e][t]);
            atomicAdd(&sacc[a2 + e * 32][og * 7 + t].x, A.x - Bv.y);
            atomicAdd(&sacc[a2 + e * 32][og * 7 + t].y, A.y + Bv.x);
        }
    if (og == 0) atomicAdd(&snoise, np);
    __syncthreads();

    if (tid < NOFF) {
        float p = 0.f;
        for (int a = 0; a < An; a++) { float2 v = sacc[a][tid]; p += v.x * v.x + v.y * v.y; }
        spwr[tid] = p;
    }
    __syncthreads();
    if (tid == 0) {
        const int ideal = ((Kc - shifts[u]) % Kc) * (Ln / Kc);
        float best = -1.f; int bj = 0;
        for (int j = 0; j < NOFF; j++) if (spwr[j] > best) { best = spwr[j]; bj = j; } // first max wins
        g_m[u][b] = ideal + bj - 10;
        g_noise[u][b] = snoise * (0.5f / (float)(An * (Ln - 1)));
    }
}

// ---------------- K2: 12x12 Wiener matrix (double GJ) + phasor table, per (u,b) ------
__global__ void k2_prep() {
    const int u = blockIdx.x / Bn, b = blockIdx.x % Bn;
    const int tid = threadIdx.x;
    __shared__ double M[12][25];
    __shared__ double Cs[12][12];
    __shared__ double pv;
    __shared__ double fac[12];

    const double s = (double)g_noise[u][b];
    for (int i = tid; i < 144; i += 128) {
        int r = i / 12, c = i % 12;
        int d = r > c ? r - c : c - r;
        double p = 1.0;
        for (int q = 0; q < d; q++) p *= 0.9;
        Cs[r][c] = p;
    }
    __syncthreads();
    for (int i = tid; i < 288; i += 128) {
        int r = i / 24, c = i % 24;
        M[r][c] = (c < 12) ? (Cs[r][c] + (r == c ? s : 0.0)) : ((c - 12) == r ? 1.0 : 0.0);
    }
    __syncthreads();
    for (int k = 0; k < 12; k++) {            // SPD: no pivoting needed
        if (tid == 0) pv = 1.0 / M[k][k];
        __syncthreads();
        for (int c = tid; c < 24; c += 128) M[k][c] *= pv;
        __syncthreads();
        if (tid < 12) fac[tid] = M[tid][k];
        __syncthreads();
        for (int i = tid; i < 288; i += 128) {
            int r = i / 24, c = i % 24;
            if (r != k) M[r][c] -= fac[r] * M[k][c];
        }
        __syncthreads();
    }
    for (int i = tid; i < 144; i += 128) {    // W = C * inv(C + sI)
        int r = i / 12, c = i % 12;
        double w = 0.0;
        for (int k = 0; k < 12; k++) w += Cs[r][k] * M[k][12 + c];
        g_W[u][b][i] = (float)w;
    }
    int m = g_m[u][b] % Ln; if (m < 0) m += Ln;
    for (int n = tid; n < Ln; n += 128) {
        int r = (m * n) % Ln;
        double ang = 6.283185307179586476925287 * (double)r / (double)Ln;
        double sn, cs; sincos(ang, &sn, &cs);
        g_phas[u][b][n] = make_float2((float)cs, (float)sn);
    }
}

// ---------------- K3: rotate -> avg(4) -> interp -> Wiener -> output, 8 rows/block ---
__global__ __launch_bounds__(256) void k3_main(const float* __restrict__ xr_all,
                                               const float* __restrict__ xi_all,
                                               float2* __restrict__ out) {
    const int blk = blockIdx.x;
    const int u = blk / (Bn * 8);
    const int rem = blk % (Bn * 8);
    const int b = rem / 8, ag = rem % 8;
    __shared__ float2 sph[Ln];
    __shared__ ull    sW[144];
    __shared__ float2 sha[REDn];
    __shared__ float2 shi[Ln];
    const int tid = threadIdx.x;

    for (int n = tid; n < Ln; n += 256) sph[n] = g_phas[u][b][n];
    for (int i = tid; i < 144; i += 256) { float w = g_W[u][b][i]; sW[i] = pack2(w, w); }
    __syncthreads();

    for (int ai = 0; ai < 8; ai++) {
        const int a = ag * 8 + ai;
        const size_t rb = (size_t)((u * Bn + b) * An + a) * Ln;
        const float4* xr4 = (const float4*)(xr_all + rb);
        const float4* xi4 = (const float4*)(xi_all + rb);

        // phase-rotate 4 consecutive samples and average -> h_avg[g]
        for (int g = tid; g < REDn; g += 256) {
            float4 xr = xr4[g], xi = xi4[g];
            const ull* pp = (const ull*)&sph[4 * g];
            ull aA = ffma2(pack2(xr.x, xr.x), pp[0], 0ull);
            ull aB = ffma2(pack2(xi.x, xi.x), pp[0], 0ull);
            aA = ffma2(pack2(xr.y, xr.y), pp[1], aA);
            aB = ffma2(pack2(xi.y, xi.y), pp[1], aB);
            aA = ffma2(pack2(xr.z, xr.z), pp[2], aA);
            aB = ffma2(pack2(xi.z, xi.z), pp[2], aB);
            aA = ffma2(pack2(xr.w, xr.w), pp[3], aA);
            aB = ffma2(pack2(xi.w, xi.w), pp[3], aB);
            float2 A = unpack2(aA), Bv = unpack2(aB);
            sha[g] = make_float2((A.x - Bv.y) * 0.25f, (A.y + Bv.x) * 0.25f);
        }
        __syncthreads();

        // linear re-interpolation back to L
        for (int t2 = tid; t2 < Ln; t2 += 256) {
            float p = ((float)t2 - 1.5f) * 0.25f;
            p = fminf(fmaxf(p, 0.f), 407.f);
            int i0 = (int)p; if (i0 > 406) i0 = 406;
            float f = p - (float)i0;
            ull h0 = *(const ull*)&sha[i0];
            ull h1 = *(const ull*)&sha[i0 + 1];
            ull hv = ffma2(pack2(f, f), h1, fmul2(pack2(1.f - f, 1.f - f), h0));
            *(ull*)&shi[t2] = hv;
        }
        __syncthreads();

        // per-12-block Wiener filter, interleaved complex store
        float2* orow = out + rb;
        for (int t2 = tid; t2 < Ln; t2 += 256) {
            int j = t2 / 12, i = t2 - j * 12;
            const ull* hb = (const ull*)&shi[j * 12];
            ull acc = 0ull, acc2 = 0ull;
            #pragma unroll
            for (int k = 0; k < 12; k += 2) {
                acc  = ffma2(sW[i * 12 + k],     hb[k],     acc);
                acc2 = ffma2(sW[i * 12 + k + 1], hb[k + 1], acc2);
            }
            float2 A = unpack2(acc), Bv = unpack2(acc2);
            orow[t2] = make_float2(A.x + Bv.x, A.y + Bv.y);
        }
        __syncthreads();
    }
}

// ---------------- launch ----------------
extern "C" void kernel_launch(void* const* d_in, const int* in_sizes, int n_in,
                              void* d_out, int out_size) {
    (void)in_sizes; (void)n_in; (void)out_size;
    const float* xr = (const float*)d_in[0];
    const float* xi = (const float*)d_in[1];
    const int*   sh = (const int*)d_in[2];

    k0_tw  <<<UPn * NOFF, 256>>>(sh);
    k1_dft <<<UPn * Bn,   576>>>(xr, xi, sh);
    k2_prep<<<UPn * Bn,   128>>>();
    k3_main<<<UPn * Bn * 8, 256>>>(xr, xi, (float2*)d_out);
}

// round 10
// speedup vs baseline: 1.3789x; 1.3789x over previous
#include <cuda_runtime.h>

typedef unsigned long long ull;

#define UPn 8
#define Bn 32
#define An 64
#define Ln 1632
#define Kc 12
#define NOFF 21
#define NC 48
#define REDn 408

// ---------------- device scratch (static, no runtime alloc) ----------------
__device__ float2 g_tw[UPn][NOFF][Ln];     // exp(+2*pi*i*n*t/L) per (u, window point)
__device__ int    g_m[UPn][Bn];
__device__ float  g_noise[UPn][Bn];
__device__ float2 g_phas[UPn][Bn][Ln];     // exp(+i * 2pi/L * ((m*n) mod L))
__device__ float  g_W[UPn][Bn][144];       // Wiener 12x12, real

// ---------------- f32x2 helpers (sm_100+) ----------------
__device__ __forceinline__ ull ffma2(ull a, ull b, ull c) {
    ull d; asm("fma.rn.f32x2 %0, %1, %2, %3;" : "=l"(d) : "l"(a), "l"(b), "l"(c)); return d;
}
__device__ __forceinline__ ull fmul2(ull a, ull b) {
    ull d; asm("mul.rn.f32x2 %0, %1, %2;" : "=l"(d) : "l"(a), "l"(b)); return d;
}
__device__ __forceinline__ ull pack2(float lo, float hi) {
    ull d; asm("mov.b64 %0, {%1, %2};" : "=l"(d) : "f"(lo), "f"(hi)); return d;
}
__device__ __forceinline__ float2 unpack2(ull v) {
    float lo, hi; asm("mov.b64 {%0, %1}, %2;" : "=f"(lo), "=f"(hi) : "l"(v));
    return make_float2(lo, hi);
}

// 2*pi/L folded to float once (double-rounded constant)
__device__ __forceinline__ float2 unit_phase(int r) {
    // r in [0, Ln); map to [-Ln/2, Ln/2) for primary-range accuracy
    if (r >= Ln / 2) r -= Ln;
    const float w0 = (float)(6.283185307179586476925287 / (double)Ln);
    float sn, cs;
    sincosf(w0 * (float)r, &sn, &cs);
    return make_float2(cs, sn);
}

// ---------------- K0: twiddle tables for the 21-point window DFT ----------------
__global__ void k0_tw(const int* __restrict__ shifts) {
    const int u = blockIdx.x / NOFF, j = blockIdx.x % NOFF;
    const int ideal = ((Kc - shifts[u]) % Kc) * (Ln / Kc);
    int t = ideal + j - 10; t %= Ln; if (t < 0) t += Ln;
    for (int n = threadIdx.x; n < Ln; n += blockDim.x) {
        int r = (n * t) % Ln;                       // <= 1631*1631, fits int32
        g_tw[u][j][n] = unit_phase(r);
    }
}

// ---------------- K1: window DFT + power argmax + noise power, one block per (u,b) ----
__global__ __launch_bounds__(576, 1) void k1_dft(const float* __restrict__ xr_all,
                                                 const float* __restrict__ xi_all,
                                                 const int* __restrict__ shifts) {
    const int u = blockIdx.x / Bn, b = blockIdx.x % Bn;
    __shared__ float2 sx[An][NC + 3];     // +1 extra col for diffs, odd 8B stride (51)
    __shared__ float2 stw[NOFF][NC];
    __shared__ float2 sacc[An][NOFF];
    __shared__ float  spwr[NOFF];
    __shared__ float  snoise;

    const int tid = threadIdx.x;
    const int a2  = tid & 31;             // lane -> antenna (and antenna+32)
    const int wid = tid >> 5;             // 0..17
    const int og  = wid % 3;              // offset group (7 offsets each)
    const int rr  = wid / 3;              // n-residue 0..5

    for (int i = tid; i < An * NOFF; i += 576) ((float2*)sacc)[i] = make_float2(0.f, 0.f);
    if (tid < NOFF) spwr[tid] = 0.f;
    if (tid == 0) snoise = 0.f;

    const float* xr0 = xr_all + (size_t)(u * Bn + b) * An * Ln;
    const float* xi0 = xi_all + (size_t)(u * Bn + b) * An * Ln;

    ull accA[2][7], accB[2][7];
    #pragma unroll
    for (int e = 0; e < 2; e++)
        #pragma unroll
        for (int t = 0; t < 7; t++) { accA[e][t] = 0ull; accB[e][t] = 0ull; }
    float np = 0.f;

    for (int c0 = 0; c0 < Ln; c0 += NC) {
        __syncthreads();
        for (int i = tid; i < An * NC; i += 576) {
            int a = i / NC, n = i - a * NC;
            sx[a][n] = make_float2(xr0[(size_t)a * Ln + c0 + n],
                                   xi0[(size_t)a * Ln + c0 + n]);
        }
        if (c0 + NC < Ln && tid < An)
            sx[tid][NC] = make_float2(xr0[(size_t)tid * Ln + c0 + NC],
                                      xi0[(size_t)tid * Ln + c0 + NC]);
        for (int i = tid; i < NOFF * NC; i += 576) {
            int o = i / NC, n = i - o * NC;
            stw[o][n] = g_tw[u][o][c0 + n];
        }
        __syncthreads();

        for (int n = rr; n < NC; n += 6) {
            ull tw[7];
            #pragma unroll
            for (int t = 0; t < 7; t++) tw[t] = *(const ull*)&stw[og * 7 + t][n];
            #pragma unroll
            for (int e = 0; e < 2; e++) {
                const int a = a2 + e * 32;
                const float2 x = sx[a][n];
                const ull xrp = pack2(x.x, x.x);
                const ull xip = pack2(x.y, x.y);
                #pragma unroll
                for (int t = 0; t < 7; t++) {
                    accA[e][t] = ffma2(xrp, tw[t], accA[e][t]);
                    accB[e][t] = ffma2(xip, tw[t], accB[e][t]);
                }
                if (og == 0 && c0 + n < Ln - 1) {   // each left index covered once
                    float2 x1 = sx[a][n + 1];
                    float dr = x1.x - x.x, di = x1.y - x.y;
                    np += dr * dr + di * di;
                }
            }
        }
    }
    __syncthreads();

    // combine packed accumulators -> complex, reduce over n-residues via smem atomics
    #pragma unroll
    for (int e = 0; e < 2; e++)
        #pragma unroll
        for (int t = 0; t < 7; t++) {
            float2 A = unpack2(accA[e][t]), Bv = unpack2(accB[e][t]);
            atomicAdd(&sacc[a2 + e * 32][og * 7 + t].x, A.x - Bv.y);
            atomicAdd(&sacc[a2 + e * 32][og * 7 + t].y, A.y + Bv.x);
        }
    if (og == 0) atomicAdd(&snoise, np);
    __syncthreads();

    if (tid < NOFF) {
        float p = 0.f;
        for (int a = 0; a < An; a++) { float2 v = sacc[a][tid]; p += v.x * v.x + v.y * v.y; }
        spwr[tid] = p;
    }
    __syncthreads();
    if (tid == 0) {
        const int ideal = ((Kc - shifts[u]) % Kc) * (Ln / Kc);
        float best = -1.f; int bj = 0;
        for (int j = 0; j < NOFF; j++) if (spwr[j] > best) { best = spwr[j]; bj = j; } // first max wins
        g_m[u][b] = ideal + bj - 10;
        g_noise[u][b] = snoise * (0.5f / (float)(An * (Ln - 1)));
    }
}

// ---------------- K2: 12x12 Wiener matrix (double GJ) + phasor table, per (u,b) ------
__global__ void k2_prep() {
    const int u = blockIdx.x / Bn, b = blockIdx.x % Bn;
    const int tid = threadIdx.x;
    __shared__ double M[12][25];
    __shared__ double Cs[12][12];
    __shared__ double pv;
    __shared__ double fac[12];

    const double s = (double)g_noise[u][b];
    for (int i = tid; i < 144; i += 128) {
        int r = i / 12, c = i % 12;
        int d = r > c ? r - c : c - r;
        double p = 1.0;
        for (int q = 0; q < d; q++) p *= 0.9;
        Cs[r][c] = p;
    }
    __syncthreads();
    for (int i = tid; i < 288; i += 128) {
        int r = i / 24, c = i % 24;
        M[r][c] = (c < 12) ? (Cs[r][c] + (r == c ? s : 0.0)) : ((c - 12) == r ? 1.0 : 0.0);
    }
    __syncthreads();
    for (int k = 0; k < 12; k++) {            // SPD: no pivoting needed
        if (tid == 0) pv = 1.0 / M[k][k];
        __syncthreads();
        for (int c = tid; c < 24; c += 128) M[k][c] *= pv;
        __syncthreads();
        if (tid < 12) fac[tid] = M[tid][k];
        __syncthreads();
        for (int i = tid; i < 288; i += 128) {
            int r = i / 24, c = i % 24;
            if (r != k) M[r][c] -= fac[r] * M[k][c];
        }
        __syncthreads();
    }
    for (int i = tid; i < 144; i += 128) {    // W = C * inv(C + sI)
        int r = i / 12, c = i % 12;
        double w = 0.0;
        for (int k = 0; k < 12; k++) w += Cs[r][k] * M[k][12 + c];
        g_W[u][b][i] = (float)w;
    }
    int m = g_m[u][b] % Ln; if (m < 0) m += Ln;
    for (int n = tid; n < Ln; n += 128) {
        int r = (m * n) % Ln;
        g_phas[u][b][n] = unit_phase(r);
    }
}

// ---------------- K3: rotate -> avg(4) -> interp -> Wiener -> output ----------------
// 8 antennas per block, processed 2 at a time. Fixed thread role: i = tid%12 is the
// output-within-12-block index; Wiener row W[i][*] lives in registers (no smem W).
__global__ __launch_bounds__(256) void k3_main(const float* __restrict__ xr_all,
                                               const float* __restrict__ xi_all,
                                               float2* __restrict__ out) {
    const int blk = blockIdx.x;
    const int u = blk / (Bn * 8);
    const int rem = blk % (Bn * 8);
    const int b = rem / 8, ag = rem % 8;

    __shared__ float2 sph[Ln];          // 13056 B
    __shared__ float2 sha[2][REDn];     //  6528 B
    __shared__ ull    shi[2][Ln];       // 26112 B  (45.7 KB total)

    const int tid = threadIdx.x;
    const int i12 = tid % 12;
    const int grp = tid / 12;           // 0..20 active in Wiener stage; 21 idle

    for (int n = tid; n < Ln; n += 256) sph[n] = g_phas[u][b][n];

    ull Wr[12];
    {
        const float* Wrow = &g_W[u][b][i12 * 12];
        #pragma unroll
        for (int k = 0; k < 12; k++) { float w = Wrow[k]; Wr[k] = pack2(w, w); }
    }
    __syncthreads();

    for (int pass = 0; pass < 4; pass++) {
        const int a0 = ag * 8 + pass * 2;
        const size_t rb0 = (size_t)((u * Bn + b) * An + a0) * Ln;

        // stage A: phase-rotate 4 consecutive samples and average -> sha[ai][g]
        for (int idx = tid; idx < 2 * REDn; idx += 256) {
            const int ai = idx / REDn, g = idx - ai * REDn;
            const float4* xr4 = (const float4*)(xr_all + rb0 + (size_t)ai * Ln);
            const float4* xi4 = (const float4*)(xi_all + rb0 + (size_t)ai * Ln);
            float4 xr = xr4[g], xi = xi4[g];
            const ull* pp = (const ull*)&sph[4 * g];
            ull aA = ffma2(pack2(xr.x, xr.x), pp[0], 0ull);
            ull aB = ffma2(pack2(xi.x, xi.x), pp[0], 0ull);
            aA = ffma2(pack2(xr.y, xr.y), pp[1], aA);
            aB = ffma2(pack2(xi.y, xi.y), pp[1], aB);
            aA = ffma2(pack2(xr.z, xr.z), pp[2], aA);
            aB = ffma2(pack2(xi.z, xi.z), pp[2], aB);
            aA = ffma2(pack2(xr.w, xr.w), pp[3], aA);
            aB = ffma2(pack2(xi.w, xi.w), pp[3], aB);
            float2 A = unpack2(aA), Bv = unpack2(aB);
            sha[ai][g] = make_float2((A.x - Bv.y) * 0.25f, (A.y + Bv.x) * 0.25f);
        }
        __syncthreads();

        // stage B1: linear re-interpolation back to L
        for (int idx = tid; idx < 2 * Ln; idx += 256) {
            const int ai = idx / Ln, t2 = idx - ai * Ln;
            float p = ((float)t2 - 1.5f) * 0.25f;
            p = fminf(fmaxf(p, 0.f), 407.f);
            int i0 = (int)p; if (i0 > 406) i0 = 406;
            float f = p - (float)i0;
            ull h0 = *(const ull*)&sha[ai][i0];
            ull h1 = *(const ull*)&sha[ai][i0 + 1];
            shi[ai][t2] = ffma2(pack2(f, f), h1, fmul2(pack2(1.f - f, 1.f - f), h0));
        }
        __syncthreads();

        // stage B2: Wiener filter; each 12-thread group owns one (ai, jb) block,
        // thread computes output i12.  h loads via 3x LDS.128 broadcast, W in regs.
        if (grp < 21) {
            for (int task = grp; task < 2 * 136; task += 21) {
                const int ai = task / 136, jb = task - ai * 136;
                const uint4* hb4 = (const uint4*)&shi[ai][jb * 12];
                ull acc0 = 0ull, acc1 = 0ull;
                #pragma unroll
                for (int q = 0; q < 6; q++) {
                    uint4 hv = hb4[q];
                    ull ha = ((ull)hv.y << 32) | hv.x;
                    ull hbv = ((ull)hv.w << 32) | hv.z;
                    acc0 = ffma2(Wr[2 * q],     ha,  acc0);
                    acc1 = ffma2(Wr[2 * q + 1], hbv, acc1);
                }
                float2 A = unpack2(acc0), Bv = unpack2(acc1);
                out[rb0 + (size_t)ai * Ln + jb * 12 + i12] =
                    make_float2(A.x + Bv.x, A.y + Bv.y);
            }
        }
        __syncthreads();
    }
}

// ---------------- launch ----------------
extern "C" void kernel_launch(void* const* d_in, const int* in_sizes, int n_in,
                              void* d_out, int out_size) {
    (void)in_sizes; (void)n_in; (void)out_size;
    const float* xr = (const float*)d_in[0];
    const float* xi = (const float*)d_in[1];
    const int*   sh = (const int*)d_in[2];

    k0_tw  <<<UPn * NOFF, 256>>>(sh);
    k1_dft <<<UPn * Bn,   576>>>(xr, xi, sh);
    k2_prep<<<UPn * Bn,   128>>>();
    k3_main<<<UPn * Bn * 8, 256>>>(xr, xi, (float2*)d_out);
}

// round 11
// speedup vs baseline: 2.1102x; 1.5304x over previous
#include <cuda_runtime.h>

typedef unsigned long long ull;

#define UPn 8
#define Bn 32
#define An 64
#define Ln 1632
#define Kc 12
#define NOFF 21
#define NC 48
#define REDn 408

// ---------------- device scratch (static, no runtime alloc) ----------------
__device__ float2 g_tw[UPn][NOFF][Ln];     // exp(+2*pi*i*n*t/L) per (u, window point)
__device__ int    g_m[UPn][Bn];
__device__ float  g_noise[UPn][Bn];
__device__ float2 g_phas[UPn][Bn][Ln];     // exp(+i * 2pi/L * ((m*n) mod L))
__device__ float  g_W[UPn][Bn][144];       // Wiener 12x12, real

// ---------------- f32x2 helpers (sm_100+) ----------------
__device__ __forceinline__ ull ffma2(ull a, ull b, ull c) {
    ull d; asm("fma.rn.f32x2 %0, %1, %2, %3;" : "=l"(d) : "l"(a), "l"(b), "l"(c)); return d;
}
__device__ __forceinline__ ull fmul2(ull a, ull b) {
    ull d; asm("mul.rn.f32x2 %0, %1, %2;" : "=l"(d) : "l"(a), "l"(b)); return d;
}
__device__ __forceinline__ ull pack2(float lo, float hi) {
    ull d; asm("mov.b64 %0, {%1, %2};" : "=l"(d) : "f"(lo), "f"(hi)); return d;
}
__device__ __forceinline__ float2 unpack2(ull v) {
    float lo, hi; asm("mov.b64 {%0, %1}, %2;" : "=f"(lo), "=f"(hi) : "l"(v));
    return make_float2(lo, hi);
}

// 2*pi/L folded to float once (double-rounded constant)
__device__ __forceinline__ float2 unit_phase(int r) {
    // r in [0, Ln); map to [-Ln/2, Ln/2) for primary-range accuracy
    if (r >= Ln / 2) r -= Ln;
    const float w0 = (float)(6.283185307179586476925287 / (double)Ln);
    float sn, cs;
    sincosf(w0 * (float)r, &sn, &cs);
    return make_float2(cs, sn);
}

// ---------------- K0: twiddle tables for the 21-point window DFT ----------------
__global__ void k0_tw(const int* __restrict__ shifts) {
    const int u = blockIdx.x / NOFF, j = blockIdx.x % NOFF;
    const int ideal = ((Kc - shifts[u]) % Kc) * (Ln / Kc);
    int t = ideal + j - 10; t %= Ln; if (t < 0) t += Ln;
    for (int n = threadIdx.x; n < Ln; n += blockDim.x) {
        int r = (n * t) % Ln;                       // <= 1631*1631, fits int32
        g_tw[u][j][n] = unit_phase(r);
    }
}

// ---------------- K1: window DFT + power argmax + noise power, one block per (u,b) ----
// 288 threads (9 warps): og = wid%3 (7-offset group), rr = wid/3 (n-residue, step 3).
// 2 blocks co-resident per SM -> one block's DRAM load phase overlaps the other's
// compute phase, and 256 blocks fit a single wave (296 slots).
__global__ __launch_bounds__(288, 2) void k1_dft(const float* __restrict__ xr_all,
                                                 const float* __restrict__ xi_all,
                                                 const int* __restrict__ shifts) {
    const int u = blockIdx.x / Bn, b = blockIdx.x % Bn;
    __shared__ float2 sx[An][NC + 3];     // +1 extra col for diffs, odd 8B stride (51)
    __shared__ float2 stw[NOFF][NC];
    __shared__ float2 sacc[An][NOFF];
    __shared__ float  spwr[NOFF];
    __shared__ float  snoise;

    const int tid = threadIdx.x;
    const int a2  = tid & 31;             // lane -> antenna (and antenna+32)
    const int wid = tid >> 5;             // 0..8
    const int og  = wid % 3;              // offset group (7 offsets each)
    const int rr  = wid / 3;              // n-residue 0..2

    for (int i = tid; i < An * NOFF; i += 288) ((float2*)sacc)[i] = make_float2(0.f, 0.f);
    if (tid < NOFF) spwr[tid] = 0.f;
    if (tid == 0) snoise = 0.f;

    const float* xr0 = xr_all + (size_t)(u * Bn + b) * An * Ln;
    const float* xi0 = xi_all + (size_t)(u * Bn + b) * An * Ln;

    ull accA[2][7], accB[2][7];
    #pragma unroll
    for (int e = 0; e < 2; e++)
        #pragma unroll
        for (int t = 0; t < 7; t++) { accA[e][t] = 0ull; accB[e][t] = 0ull; }
    float np = 0.f;

    for (int c0 = 0; c0 < Ln; c0 += NC) {
        __syncthreads();
        #pragma unroll 4
        for (int i = tid; i < An * NC; i += 288) {
            int a = i / NC, n = i - a * NC;
            sx[a][n] = make_float2(xr0[(size_t)a * Ln + c0 + n],
                                   xi0[(size_t)a * Ln + c0 + n]);
        }
        if (c0 + NC < Ln && tid < An)
            sx[tid][NC] = make_float2(xr0[(size_t)tid * Ln + c0 + NC],
                                      xi0[(size_t)tid * Ln + c0 + NC]);
        #pragma unroll 4
        for (int i = tid; i < NOFF * NC; i += 288) {
            int o = i / NC, n = i - o * NC;
            stw[o][n] = g_tw[u][o][c0 + n];
        }
        __syncthreads();

        for (int n = rr; n < NC; n += 3) {
            ull tw[7];
            #pragma unroll
            for (int t = 0; t < 7; t++) tw[t] = *(const ull*)&stw[og * 7 + t][n];
            #pragma unroll
            for (int e = 0; e < 2; e++) {
                const int a = a2 + e * 32;
                const float2 x = sx[a][n];
                const ull xrp = pack2(x.x, x.x);
                const ull xip = pack2(x.y, x.y);
                #pragma unroll
                for (int t = 0; t < 7; t++) {
                    accA[e][t] = ffma2(xrp, tw[t], accA[e][t]);
                    accB[e][t] = ffma2(xip, tw[t], accB[e][t]);
                }
                if (og == 0 && c0 + n < Ln - 1) {   // each left index covered once
                    float2 x1 = sx[a][n + 1];
                    float dr = x1.x - x.x, di = x1.y - x.y;
                    np += dr * dr + di * di;
                }
            }
        }
    }
    __syncthreads();

    // combine packed accumulators -> complex, reduce over n-residues via smem atomics
    #pragma unroll
    for (int e = 0; e < 2; e++)
        #pragma unroll
        for (int t = 0; t < 7; t++) {
            float2 A = unpack2(accA[e][t]), Bv = unpack2(accB[e][t]);
            atomicAdd(&sacc[a2 + e * 32][og * 7 + t].x, A.x - Bv.y);
            atomicAdd(&sacc[a2 + e * 32][og * 7 + t].y, A.y + Bv.x);
        }
    if (og == 0) atomicAdd(&snoise, np);
    __syncthreads();

    if (tid < NOFF) {
        float p = 0.f;
        for (int a = 0; a < An; a++) { float2 v = sacc[a][tid]; p += v.x * v.x + v.y * v.y; }
        spwr[tid] = p;
    }
    __syncthreads();
    if (tid == 0) {
        const int ideal = ((Kc - shifts[u]) % Kc) * (Ln / Kc);
        float best = -1.f; int bj = 0;
        for (int j = 0; j < NOFF; j++) if (spwr[j] > best) { best = spwr[j]; bj = j; } // first max wins
        g_m[u][b] = ideal + bj - 10;
        g_noise[u][b] = snoise * (0.5f / (float)(An * (Ln - 1)));
    }
}

// ---------------- K2: 12x12 Wiener matrix (double GJ) + phasor table, per (u,b) ------
__global__ void k2_prep() {
    const int u = blockIdx.x / Bn, b = blockIdx.x % Bn;
    const int tid = threadIdx.x;
    __shared__ double M[12][25];
    __shared__ double Cs[12][12];
    __shared__ double pv;
    __shared__ double fac[12];

    const double s = (double)g_noise[u][b];
    for (int i = tid; i < 144; i += 128) {
        int r = i / 12, c = i % 12;
        int d = r > c ? r - c : c - r;
        double p = 1.0;
        for (int q = 0; q < d; q++) p *= 0.9;
        Cs[r][c] = p;
    }
    __syncthreads();
    for (int i = tid; i < 288; i += 128) {
        int r = i / 24, c = i % 24;
        M[r][c] = (c < 12) ? (Cs[r][c] + (r == c ? s : 0.0)) : ((c - 12) == r ? 1.0 : 0.0);
    }
    __syncthreads();
    for (int k = 0; k < 12; k++) {            // SPD: no pivoting needed
        if (tid == 0) pv = 1.0 / M[k][k];
        __syncthreads();
        for (int c = tid; c < 24; c += 128) M[k][c] *= pv;
        __syncthreads();
        if (tid < 12) fac[tid] = M[tid][k];
        __syncthreads();
        for (int i = tid; i < 288; i += 128) {
            int r = i / 24, c = i % 24;
            if (r != k) M[r][c] -= fac[r] * M[k][c];
        }
        __syncthreads();
    }
    for (int i = tid; i < 144; i += 128) {    // W = C * inv(C + sI)
        int r = i / 12, c = i % 12;
        double w = 0.0;
        for (int k = 0; k < 12; k++) w += Cs[r][k] * M[k][12 + c];
        g_W[u][b][i] = (float)w;
    }
    int m = g_m[u][b] % Ln; if (m < 0) m += Ln;
    for (int n = tid; n < Ln; n += 128) {
        int r = (m * n) % Ln;
        g_phas[u][b][n] = unit_phase(r);
    }
}

// ---------------- K3: rotate -> avg(4) -> interp -> Wiener -> output ----------------
// 8 antennas per block, processed 2 at a time. Fixed thread role: i = tid%12 is the
// output-within-12-block index; Wiener row W[i][*] lives in registers (no smem W).
__global__ __launch_bounds__(256) void k3_main(const float* __restrict__ xr_all,
                                               const float* __restrict__ xi_all,
                                               float2* __restrict__ out) {
    const int blk = blockIdx.x;
    const int u = blk / (Bn * 8);
    const int rem = blk % (Bn * 8);
    const int b = rem / 8, ag = rem % 8;

    __shared__ float2 sph[Ln];          // 13056 B
    __shared__ float2 sha[2][REDn];     //  6528 B
    __shared__ ull    shi[2][Ln];       // 26112 B  (45.7 KB total)

    const int tid = threadIdx.x;
    const int i12 = tid % 12;
    const int grp = tid / 12;           // 0..20 active in Wiener stage; 21 idle

    for (int n = tid; n < Ln; n += 256) sph[n] = g_phas[u][b][n];

    ull Wr[12];
    {
        const float* Wrow = &g_W[u][b][i12 * 12];
        #pragma unroll
        for (int k = 0; k < 12; k++) { float w = Wrow[k]; Wr[k] = pack2(w, w); }
    }
    __syncthreads();

    for (int pass = 0; pass < 4; pass++) {
        const int a0 = ag * 8 + pass * 2;
        const size_t rb0 = (size_t)((u * Bn + b) * An + a0) * Ln;

        // stage A: phase-rotate 4 consecutive samples and average -> sha[ai][g]
        for (int idx = tid; idx < 2 * REDn; idx += 256) {
            const int ai = idx / REDn, g = idx - ai * REDn;
            const float4* xr4 = (const float4*)(xr_all + rb0 + (size_t)ai * Ln);
            const float4* xi4 = (const float4*)(xi_all + rb0 + (size_t)ai * Ln);
            float4 xr = xr4[g], xi = xi4[g];
            const ull* pp = (const ull*)&sph[4 * g];
            ull aA = ffma2(pack2(xr.x, xr.x), pp[0], 0ull);
            ull aB = ffma2(pack2(xi.x, xi.x), pp[0], 0ull);
            aA = ffma2(pack2(xr.y, xr.y), pp[1], aA);
            aB = ffma2(pack2(xi.y, xi.y), pp[1], aB);
            aA = ffma2(pack2(xr.z, xr.z), pp[2], aA);
            aB = ffma2(pack2(xi.z, xi.z), pp[2], aB);
            aA = ffma2(pack2(xr.w, xr.w), pp[3], aA);
            aB = ffma2(pack2(xi.w, xi.w), pp[3], aB);
            float2 A = unpack2(aA), Bv = unpack2(aB);
            sha[ai][g] = make_float2((A.x - Bv.y) * 0.25f, (A.y + Bv.x) * 0.25f);
        }
        __syncthreads();

        // stage B1: linear re-interpolation back to L
        for (int idx = tid; idx < 2 * Ln; idx += 256) {
            const int ai = idx / Ln, t2 = idx - ai * Ln;
            float p = ((float)t2 - 1.5f) * 0.25f;
            p = fminf(fmaxf(p, 0.f), 407.f);
            int i0 = (int)p; if (i0 > 406) i0 = 406;
            float f = p - (float)i0;
            ull h0 = *(const ull*)&sha[ai][i0];
            ull h1 = *(const ull*)&sha[ai][i0 + 1];
            shi[ai][t2] = ffma2(pack2(f, f), h1, fmul2(pack2(1.f - f, 1.f - f), h0));
        }
        __syncthreads();

        // stage B2: Wiener filter; each 12-thread group owns one (ai, jb) block,
        // thread computes output i12.  h loads via 3x LDS.128 broadcast, W in regs.
        if (grp < 21) {
            for (int task = grp; task < 2 * 136; task += 21) {
                const int ai = task / 136, jb = task - ai * 136;
                const uint4* hb4 = (const uint4*)&shi[ai][jb * 12];
                ull acc0 = 0ull, acc1 = 0ull;
                #pragma unroll
                for (int q = 0; q < 6; q++) {
                    uint4 hv = hb4[q];
                    ull ha = ((ull)hv.y << 32) | hv.x;
                    ull hbv = ((ull)hv.w << 32) | hv.z;
                    acc0 = ffma2(Wr[2 * q],     ha,  acc0);
                    acc1 = ffma2(Wr[2 * q + 1], hbv, acc1);
                }
                float2 A = unpack2(acc0), Bv = unpack2(acc1);
                out[rb0 + (size_t)ai * Ln + jb * 12 + i12] =
                    make_float2(A.x + Bv.x, A.y + Bv.y);
            }
        }
        __syncthreads();
    }
}

// ---------------- launch ----------------
extern "C" void kernel_launch(void* const* d_in, const int* in_sizes, int n_in,
                              void* d_out, int out_size) {
    (void)in_sizes; (void)n_in; (void)out_size;
    const float* xr = (const float*)d_in[0];
    const float* xi = (const float*)d_in[1];
    const int*   sh = (const int*)d_in[2];

    k0_tw  <<<UPn * NOFF, 256>>>(sh);
    k1_dft <<<UPn * Bn,   288>>>(xr, xi, sh);
    k2_prep<<<UPn * Bn,   128>>>();
    k3_main<<<UPn * Bn * 8, 256>>>(xr, xi, (float2*)d_out);
}

// round 15
// speedup vs baseline: 2.4040x; 1.1392x over previous
#include <cuda_runtime.h>
#include <cstdint>

typedef unsigned long long ull;

#define UPn 8
#define Bn 32
#define An 64
#define Ln 1632
#define Kc 12
#define NOFF 21
#define NC 24
#define NCH (Ln / NC)            // 68 chunks
#define REDn 408

// ---------------- device scratch (static, no runtime alloc) ----------------
__device__ float2 g_tw[UPn][NOFF][Ln];     // exp(+2*pi*i*n*t/L) per (u, window point)
__device__ int    g_m[UPn][Bn];
__device__ float  g_noise[UPn][Bn];
__device__ float2 g_phas[UPn][Bn][Ln];     // exp(+i * 2pi/L * ((m*n) mod L))
__device__ float  g_W[UPn][Bn][144];       // Wiener 12x12, real

// ---------------- f32x2 helpers (sm_100+) ----------------
__device__ __forceinline__ ull ffma2(ull a, ull b, ull c) {
    ull d; asm("fma.rn.f32x2 %0, %1, %2, %3;" : "=l"(d) : "l"(a), "l"(b), "l"(c)); return d;
}
__device__ __forceinline__ ull fmul2(ull a, ull b) {
    ull d; asm("mul.rn.f32x2 %0, %1, %2;" : "=l"(d) : "l"(a), "l"(b)); return d;
}
__device__ __forceinline__ ull pack2(float lo, float hi) {
    ull d; asm("mov.b64 %0, {%1, %2};" : "=l"(d) : "f"(lo), "f"(hi)); return d;
}
__device__ __forceinline__ float2 unpack2(ull v) {
    float lo, hi; asm("mov.b64 {%0, %1}, %2;" : "=f"(lo), "=f"(hi) : "l"(v));
    return make_float2(lo, hi);
}

// cp.async helpers
__device__ __forceinline__ uint32_t s2u(const void* p) {
    return (uint32_t)__cvta_generic_to_shared(p);
}
__device__ __forceinline__ void cpa4(uint32_t dst, const void* src) {
    asm volatile("cp.async.ca.shared.global [%0], [%1], 4;" :: "r"(dst), "l"(src));
}
__device__ __forceinline__ void cpa16(uint32_t dst, const void* src) {
    asm volatile("cp.async.ca.shared.global [%0], [%1], 16;" :: "r"(dst), "l"(src));
}

// 2*pi/L folded to float once (double-rounded constant)
__device__ __forceinline__ float2 unit_phase(int r) {
    if (r >= Ln / 2) r -= Ln;
    const float w0 = (float)(6.283185307179586476925287 / (double)Ln);
    float sn, cs;
    sincosf(w0 * (float)r, &sn, &cs);
    return make_float2(cs, sn);
}

// ---------------- K0: twiddle tables for the 21-point window DFT ----------------
__global__ void k0_tw(const int* __restrict__ shifts) {
    const int u = blockIdx.x / NOFF, j = blockIdx.x % NOFF;
    const int ideal = ((Kc - shifts[u]) % Kc) * (Ln / Kc);
    int t = ideal + j - 10; t %= Ln; if (t < 0) t += Ln;
    for (int n = threadIdx.x; n < Ln; n += blockDim.x) {
        int r = (n * t) % Ln;                       // <= 1631*1631, fits int32
        g_tw[u][j][n] = unit_phase(r);
    }
}

// ---------------- K1: window DFT + argmax + noise, cp.async double-buffered ---------
// 288 threads (9 warps): og = wid%3 (7-offset group), rr = wid/3 (n-residue mod 3).
// 2 blocks/SM, single wave.  Chunk c+1 prefetched via cp.async while computing c.
__global__ __launch_bounds__(288, 2) void k1_dft(const float* __restrict__ xr_all,
                                                 const float* __restrict__ xi_all,
                                                 const int* __restrict__ shifts) {
    const int u = blockIdx.x / Bn, b = blockIdx.x % Bn;
    __shared__ float  sxr[2][An][NC + 1];            // 12800 B (25-float rows: odd, conflict-free)
    __shared__ float  sxi[2][An][NC + 1];            // 12800 B
    __shared__ __align__(16) float2 stw[2][NOFF][NC];// 8064 B
    __shared__ float2 sacc[An][NOFF];                // 10752 B
    __shared__ float  spwr[NOFF];
    __shared__ float  snoise;

    const int tid = threadIdx.x;
    const int a2  = tid & 31;             // lane -> antenna (and antenna+32)
    const int wid = tid >> 5;             // 0..8
    const int og  = wid % 3;              // offset group (7 offsets each)
    const int rr  = wid / 3;              // n-residue 0..2

    for (int i = tid; i < An * NOFF; i += 288) ((float2*)sacc)[i] = make_float2(0.f, 0.f);
    if (tid < NOFF) spwr[tid] = 0.f;
    if (tid == 0) snoise = 0.f;

    const float* xr0 = xr_all + (size_t)(u * Bn + b) * An * Ln;
    const float* xi0 = xi_all + (size_t)(u * Bn + b) * An * Ln;

    const uint32_t sxr_u = s2u(&sxr[0][0][0]);
    const uint32_t sxi_u = s2u(&sxi[0][0][0]);
    const uint32_t stw_u = s2u(&stw[0][0][0]);

    auto prefetch = [&](int c, int buf) {
        const int c0 = c * NC;
        const uint32_t xb = (uint32_t)(buf * An * (NC + 1)) * 4u;
        for (int i = tid; i < An * NC; i += 288) {
            int a = i / NC, n = i - a * NC;
            uint32_t off = xb + (uint32_t)(a * (NC + 1) + n) * 4u;
            cpa4(sxr_u + off, xr0 + (size_t)a * Ln + c0 + n);
            cpa4(sxi_u + off, xi0 + (size_t)a * Ln + c0 + n);
        }
        if (tid < An && c0 + NC < Ln) {              // halo col for the noise diff
            uint32_t off = xb + (uint32_t)(tid * (NC + 1) + NC) * 4u;
            cpa4(sxr_u + off, xr0 + (size_t)tid * Ln + c0 + NC);
            cpa4(sxi_u + off, xi0 + (size_t)tid * Ln + c0 + NC);
        }
        if (tid < NOFF * (NC / 2)) {                 // 252 x 16B ops for twiddles
            int o = tid / (NC / 2), q = tid - o * (NC / 2);
            cpa16(stw_u + (uint32_t)(buf * NOFF * NC + o * NC + q * 2) * 8u,
                  &g_tw[u][o][c0 + q * 2]);
        }
    };

    ull accA[2][7], accB[2][7];
    #pragma unroll
    for (int e = 0; e < 2; e++)
        #pragma unroll
        for (int t = 0; t < 7; t++) { accA[e][t] = 0ull; accB[e][t] = 0ull; }
    float np = 0.f;

    prefetch(0, 0);
    asm volatile("cp.async.commit_group;");

    for (int c = 0; c < NCH; c++) {
        const int buf = c & 1;
        const int c0 = c * NC;
        if (c + 1 < NCH) {
            prefetch(c + 1, buf ^ 1);
            asm volatile("cp.async.commit_group;");
            asm volatile("cp.async.wait_group 1;");
        } else {
            asm volatile("cp.async.wait_group 0;");
        }
        __syncthreads();

        for (int n = rr; n < NC; n += 3) {
            ull tw[7];
            #pragma unroll
            for (int t = 0; t < 7; t++) tw[t] = *(const ull*)&stw[buf][og * 7 + t][n];
            #pragma unroll
            for (int e = 0; e < 2; e++) {
                const int a = a2 + e * 32;
                const float xrv = sxr[buf][a][n];
                const float xiv = sxi[buf][a][n];
                const ull xrp = pack2(xrv, xrv);
                const ull xip = pack2(xiv, xiv);
                #pragma unroll
                for (int t = 0; t < 7; t++) {
                    accA[e][t] = ffma2(xrp, tw[t], accA[e][t]);
                    accB[e][t] = ffma2(xip, tw[t], accB[e][t]);
                }
                if (og == 0 && c0 + n < Ln - 1) {   // each left index covered once
                    float dr = sxr[buf][a][n + 1] - xrv;
                    float di = sxi[buf][a][n + 1] - xiv;
                    np += dr * dr + di * di;
                }
            }
        }
        __syncthreads();   // all reads of this buffer done before it is refilled
    }

    // combine packed accumulators -> complex, reduce over n-residues via smem atomics
    #pragma unroll
    for (int e = 0; e < 2; e++)
        #pragma unroll
        for (int t = 0; t < 7; t++) {
            float2 A = unpack2(accA[e][t]), Bv = unpack2(accB[e][t]);
            atomicAdd(&sacc[a2 + e * 32][og * 7 + t].x, A.x - Bv.y);
            atomicAdd(&sacc[a2 + e * 32][og * 7 + t].y, A.y + Bv.x);
        }
    if (og == 0) atomicAdd(&snoise, np);
    __syncthreads();

    if (tid < NOFF) {
        float p = 0.f;
        for (int a = 0; a < An; a++) { float2 v = sacc[a][tid]; p += v.x * v.x + v.y * v.y; }
        spwr[tid] = p;
    }
    __syncthreads();
    if (tid == 0) {
        const int ideal = ((Kc - shifts[u]) % Kc) * (Ln / Kc);
        float best = -1.f; int bj = 0;
        for (int j = 0; j < NOFF; j++) if (spwr[j] > best) { best = spwr[j]; bj = j; } // first max wins
        g_m[u][b] = ideal + bj - 10;
        g_noise[u][b] = snoise * (0.5f / (float)(An * (Ln - 1)));
    }
}

// ---------------- K2: 12x12 Wiener matrix (double GJ) + phasor table, per (u,b) ------
__global__ void k2_prep() {
    const int u = blockIdx.x / Bn, b = blockIdx.x % Bn;
    const int tid = threadIdx.x;
    __shared__ double M[12][25];
    __shared__ double Cs[12][12];
    __shared__ double pv;
    __shared__ double fac[12];

    const double s = (double)g_noise[u][b];
    for (int i = tid; i < 144; i += 128) {
        int r = i / 12, c = i % 12;
        int d = r > c ? r - c : c - r;
        double p = 1.0;
        for (int q = 0; q < d; q++) p *= 0.9;
        Cs[r][c] = p;
    }
    __syncthreads();
    for (int i = tid; i < 288; i += 128) {
        int r = i / 24, c = i % 24;
        M[r][c] = (c < 12) ? (Cs[r][c] + (r == c ? s : 0.0)) : ((c - 12) == r ? 1.0 : 0.0);
    }
    __syncthreads();
    for (int k = 0; k < 12; k++) {            // SPD: no pivoting needed
        if (tid == 0) pv = 1.0 / M[k][k];
        __syncthreads();
        for (int c = tid; c < 24; c += 128) M[k][c] *= pv;
        __syncthreads();
        if (tid < 12) fac[tid] = M[tid][k];
        __syncthreads();
        for (int i = tid; i < 288; i += 128) {
            int r = i / 24, c = i % 24;
            if (r != k) M[r][c] -= fac[r] * M[k][c];
        }
        __syncthreads();
    }
    for (int i = tid; i < 144; i += 128) {    // W = C * inv(C + sI)
        int r = i / 12, c = i % 12;
        double w = 0.0;
        for (int k = 0; k < 12; k++) w += Cs[r][k] * M[k][12 + c];
        g_W[u][b][i] = (float)w;
    }
    int m = g_m[u][b] % Ln; if (m < 0) m += Ln;
    for (int n = tid; n < Ln; n += 128) {
        int r = (m * n) % Ln;
        g_phas[u][b][n] = unit_phase(r);
    }
}

// ---------------- K3: rotate -> avg(4) -> interp -> Wiener -> output ----------------
__global__ __launch_bounds__(256) void k3_main(const float* __restrict__ xr_all,
                                               const float* __restrict__ xi_all,
                                               float2* __restrict__ out) {
    const int blk = blockIdx.x;
    const int u = blk / (Bn * 8);
    const int rem = blk % (Bn * 8);
    const int b = rem / 8, ag = rem % 8;

    __shared__ float2 sph[Ln];          // 13056 B
    __shared__ float2 sha[2][REDn];     //  6528 B
    __shared__ ull    shi[2][Ln];       // 26112 B  (45.7 KB total)

    const int tid = threadIdx.x;
    const int i12 = tid % 12;
    const int grp = tid / 12;           // 0..20 active in Wiener stage; 21 idle

    for (int n = tid; n < Ln; n += 256) sph[n] = g_phas[u][b][n];

    ull Wr[12];
    {
        const float* Wrow = &g_W[u][b][i12 * 12];
        #pragma unroll
        for (int k = 0; k < 12; k++) { float w = Wrow[k]; Wr[k] = pack2(w, w); }
    }
    __syncthreads();

    for (int pass = 0; pass < 4; pass++) {
        const int a0 = ag * 8 + pass * 2;
        const size_t rb0 = (size_t)((u * Bn + b) * An + a0) * Ln;

        // stage A: phase-rotate 4 consecutive samples and average -> sha[ai][g]
        for (int idx = tid; idx < 2 * REDn; idx += 256) {
            const int ai = idx / REDn, g = idx - ai * REDn;
            const float4* xr4 = (const float4*)(xr_all + rb0 + (size_t)ai * Ln);
            const float4* xi4 = (const float4*)(xi_all + rb0 + (size_t)ai * Ln);
            float4 xr = xr4[g], xi = xi4[g];
            const ull* pp = (const ull*)&sph[4 * g];
            ull aA = ffma2(pack2(xr.x, xr.x), pp[0], 0ull);
            ull aB = ffma2(pack2(xi.x, xi.x), pp[0], 0ull);
            aA = ffma2(pack2(xr.y, xr.y), pp[1], aA);
            aB = ffma2(pack2(xi.y, xi.y), pp[1], aB);
            aA = ffma2(pack2(xr.z, xr.z), pp[2], aA);
            aB = ffma2(pack2(xi.z, xi.z), pp[2], aB);
            aA = ffma2(pack2(xr.w, xr.w), pp[3], aA);
            aB = ffma2(pack2(xi.w, xi.w), pp[3], aB);
            float2 A = unpack2(aA), Bv = unpack2(aB);
            sha[ai][g] = make_float2((A.x - Bv.y) * 0.25f, (A.y + Bv.x) * 0.25f);
        }
        __syncthreads();

        // stage B1: linear re-interpolation back to L
        for (int idx = tid; idx < 2 * Ln; idx += 256) {
            const int ai = idx / Ln, t2 = idx - ai * Ln;
            float p = ((float)t2 - 1.5f) * 0.25f;
            p = fminf(fmaxf(p, 0.f), 407.f);
            int i0 = (int)p; if (i0 > 406) i0 = 406;
            float f = p - (float)i0;
            ull h0 = *(const ull*)&sha[ai][i0];
            ull h1 = *(const ull*)&sha[ai][i0 + 1];
            shi[ai][t2] = ffma2(pack2(f, f), h1, fmul2(pack2(1.f - f, 1.f - f), h0));
        }
        __syncthreads();

        // stage B2: Wiener filter; W rows in registers, h via LDS.128 broadcast
        if (grp < 21) {
            for (int task = grp; task < 2 * 136; task += 21) {
                const int ai = task / 136, jb = task - ai * 136;
                const uint4* hb4 = (const uint4*)&shi[ai][jb * 12];
                ull acc0 = 0ull, acc1 = 0ull;
                #pragma unroll
                for (int q = 0; q < 6; q++) {
                    uint4 hv = hb4[q];
                    ull ha = ((ull)hv.y << 32) | hv.x;
                    ull hbv = ((ull)hv.w << 32) | hv.z;
                    acc0 = ffma2(Wr[2 * q],     ha,  acc0);
                    acc1 = ffma2(Wr[2 * q + 1], hbv, acc1);
                }
                float2 A = unpack2(acc0), Bv = unpack2(acc1);
                out[rb0 + (size_t)ai * Ln + jb * 12 + i12] =
                    make_float2(A.x + Bv.x, A.y + Bv.y);
            }
        }
        __syncthreads();
    }
}

// ---------------- launch ----------------
extern "C" void kernel_launch(void* const* d_in, const int* in_sizes, int n_in,
                              void* d_out, int out_size) {
    (void)in_sizes; (void)n_in; (void)out_size;
    const float* xr = (const float*)d_in[0];
    const float* xi = (const float*)d_in[1];
    const int*   sh = (const int*)d_in[2];

    k0_tw  <<<UPn * NOFF, 256>>>(sh);
    k1_dft <<<UPn * Bn,   288>>>(xr, xi, sh);
    k2_prep<<<UPn * Bn,   128>>>();
    k3_main<<<UPn * Bn * 8, 256>>>(xr, xi, (float2*)d_out);
}